// round 2
// baseline (speedup 1.0000x reference)
#include <cuda_runtime.h>
#include <math.h>

#define B_     128
#define HID_   512
#define NG_    2048
#define VOCAB_ 1000
#define T_     256
#define GRID_  148
#define NTHR   256

#define OUT_H  (B_*T_*VOCAB_)
#define OUT_C  (OUT_H + B_*HID_)

__device__ float g_E[VOCAB_*NG_];      // embed_table @ W_ih[:,512:]^T  [1000][2048]
__device__ float g_base[B_*NG_];       // context @ W_ih[:,:512]^T + b_ih + b_hh
__device__ float g_h[2][B_*HID_];      // double-buffered hidden state
__device__ unsigned long long g_pack[2][B_];   // packed argmax (key<<32 | 999-idx)
__device__ unsigned g_bar;

__device__ __forceinline__ unsigned fkey(float x){
  unsigned u = __float_as_uint(x);
  return (u & 0x80000000u) ? ~u : (u | 0x80000000u);
}
#define DOT4(acc, a, b) acc = fmaf((a).x,(b).x, fmaf((a).y,(b).y, fmaf((a).z,(b).z, fmaf((a).w,(b).w,(acc)))))

// CTA b owns hidden units 4b..4b+3; local col cc in [0,16): gate g=cc>>2, unit u=cc&3
__device__ __forceinline__ int gcolf(int b, int cc){
  return ((cc >> 2) << 9) + (b << 2) + (cc & 3);
}

// ---------------------------------------------------------------- prologue 1
// g_E[v][g] = sum_k emb[v][k] * Wih[g][512+k]
__global__ void __launch_bounds__(256) k_E(const float* __restrict__ emb,
                                           const float* __restrict__ Wih){
  __shared__ float As[16*68], Bs[16*68];
  const int tid = threadIdx.x;
  const int tx = tid & 15, ty = tid >> 4;
  const int c0 = blockIdx.x * 64, v0 = blockIdx.y * 64;
  float acc[4][4];
#pragma unroll
  for (int i=0;i<4;++i)
#pragma unroll
    for (int j=0;j<4;++j) acc[i][j] = 0.f;

  const int rr = tid >> 2, kq = tid & 3;
  for (int kc = 0; kc < 512; kc += 16){
    int v = v0 + rr; if (v >= VOCAB_) v = VOCAB_ - 1;
    float4 a = __ldg((const float4*)(emb + (size_t)v*512 + kc + 4*kq));
    As[(4*kq+0)*68 + rr] = a.x; As[(4*kq+1)*68 + rr] = a.y;
    As[(4*kq+2)*68 + rr] = a.z; As[(4*kq+3)*68 + rr] = a.w;
    int g = c0 + rr;
    float4 b = __ldg((const float4*)(Wih + (size_t)g*1024 + 512 + kc + 4*kq));
    Bs[(4*kq+0)*68 + rr] = b.x; Bs[(4*kq+1)*68 + rr] = b.y;
    Bs[(4*kq+2)*68 + rr] = b.z; Bs[(4*kq+3)*68 + rr] = b.w;
    __syncthreads();
#pragma unroll
    for (int k = 0; k < 16; ++k){
      float4 av = *(const float4*)&As[k*68 + ty*4];
      float4 bv = *(const float4*)&Bs[k*68 + tx*4];
      float ai[4] = {av.x, av.y, av.z, av.w};
      float bj[4] = {bv.x, bv.y, bv.z, bv.w};
#pragma unroll
      for (int i=0;i<4;++i)
#pragma unroll
        for (int j=0;j<4;++j) acc[i][j] = fmaf(ai[i], bj[j], acc[i][j]);
    }
    __syncthreads();
  }
  for (int i=0;i<4;++i){
    int v = v0 + ty*4 + i;
    if (v < VOCAB_)
      for (int j=0;j<4;++j) g_E[(size_t)v*NG_ + c0 + tx*4 + j] = acc[i][j];
  }
}

// ---------------------------------------------------------------- prologue 2
// g_base[r][gcol] = sum_k ctx[r][k]*Wih[gcol][k] + b_ih + b_hh
__global__ void __launch_bounds__(256) k_base(const float* __restrict__ Wih,
                                              const float* __restrict__ bih,
                                              const float* __restrict__ bhh,
                                              const float* __restrict__ ctx){
  __shared__ float xs[128*68], ws[16*68];
  const int tid = threadIdx.x, b = blockIdx.x;
  const int tx = tid & 7, ty = tid >> 3, r0 = ty*4;
  const int gc0 = gcolf(b, 2*tx), gc1 = gcolf(b, 2*tx+1);
  float acc[4][2];
#pragma unroll
  for (int i=0;i<4;++i){ acc[i][0]=0.f; acc[i][1]=0.f; }

  for (int kc = 0; kc < 512; kc += 64){
    for (int p = 0; p < 8; ++p){
      int lin = tid + p*256; int r = lin >> 4, kq2 = lin & 15;
      *(float4*)&xs[r*68 + 4*kq2] = __ldg((const float4*)(ctx + (size_t)r*512 + kc + 4*kq2));
    }
    { int cc = tid >> 4, kq2 = tid & 15;
      *(float4*)&ws[cc*68 + 4*kq2] =
        __ldg((const float4*)(Wih + (size_t)gcolf(b,cc)*1024 + kc + 4*kq2)); }
    __syncthreads();
#pragma unroll
    for (int k4 = 0; k4 < 16; ++k4){
      int kl = 4*k4;
      float4 w0 = *(const float4*)&ws[(2*tx)*68 + kl];
      float4 w1 = *(const float4*)&ws[(2*tx+1)*68 + kl];
#pragma unroll
      for (int i=0;i<4;++i){
        float4 h4 = *(const float4*)&xs[(r0+i)*68 + kl];
        DOT4(acc[i][0], h4, w0); DOT4(acc[i][1], h4, w1);
      }
    }
    __syncthreads();
  }
  float bb0 = __ldg(bih+gc0) + __ldg(bhh+gc0);
  float bb1 = __ldg(bih+gc1) + __ldg(bhh+gc1);
  for (int i=0;i<4;++i){
    g_base[(size_t)(r0+i)*NG_ + gc0] = acc[i][0] + bb0;
    g_base[(size_t)(r0+i)*NG_ + gc1] = acc[i][1] + bb1;
  }
}

// ---------------------------------------------------------------- prologue 3
__global__ void k_init(const float* __restrict__ ctx, const int* __restrict__ sid){
  int idx = blockIdx.x*blockDim.x + threadIdx.x;
  if (idx < B_*HID_) g_h[0][idx] = ctx[idx];
  if (idx < B_) g_pack[0][idx] = (unsigned long long)(unsigned)((VOCAB_-1) - *sid);
  if (idx == 0) g_bar = 0u;
}

// ---------------------------------------------------------------- barrier
__device__ __forceinline__ void gbar(unsigned target){
  __syncthreads();
  if (threadIdx.x == 0){
    __threadfence();
    atomicAdd(&g_bar, 1u);
    while (*(volatile unsigned*)&g_bar < target) __nanosleep(32);
    __threadfence();
  }
  __syncthreads();
}

// ---------------------------------------------------------------- persistent
// smem word offsets
#define SW_HH   0                    // 16*520
#define SW_OUT  (16*520)             // 8*520
#define SH_S    (SW_OUT + 8*520)     // 128*68
#define SG_S    (SH_S + 128*68)      // 16*132
#define SC_S    (SG_S + 16*132)      // 512
#define STOK    (SC_S + 512)         // 128
#define SM_WORDS (STOK + 128)        // 23936 words = 95744 B

__global__ void __launch_bounds__(NTHR, 1) k_persist(const float* __restrict__ Whh,
                                                     const float* __restrict__ Wout,
                                                     const float* __restrict__ bout,
                                                     float* __restrict__ out){
  extern __shared__ float sm[];
  const int cta = blockIdx.x, tid = threadIdx.x;
  const int tx = tid & 7, ty = tid >> 3, r0 = ty << 2;
  const bool actA = (cta < B_);
  const bool actB = (cta < 125);
  const int gc0 = gcolf(cta, 2*tx), gc1 = gcolf(cta, 2*tx+1);
  const int colB = cta*8 + tx;

  // resident weight slices
  if (actA){
    for (int p = 0; p < 8; ++p){
      int lin = tid + p*NTHR; int cc = lin >> 7, kq = lin & 127;
      *(float4*)&sm[SW_HH + cc*520 + 4*kq] =
        __ldg((const float4*)(Whh + (size_t)gcolf(cta,cc)*HID_ + 4*kq));
    }
  }
  float boutv = 0.f;
  if (actB){
    for (int p = 0; p < 4; ++p){
      int lin = tid + p*NTHR; int cc = lin >> 7, kq = lin & 127;
      *(float4*)&sm[SW_OUT + cc*520 + 4*kq] =
        __ldg((const float4*)(Wout + (size_t)(cta*8+cc)*HID_ + 4*kq));
    }
    boutv = __ldg(bout + colB);
  }
  float basev[4][2];
  if (actA){
    for (int i=0;i<4;++i){
      basev[i][0] = __ldg(&g_base[(size_t)(r0+i)*NG_ + gc0]);
      basev[i][1] = __ldg(&g_base[(size_t)(r0+i)*NG_ + gc1]);
    }
  }
  for (int idx = tid; idx < 512; idx += NTHR) sm[SC_S + idx] = 0.f;  // cell state
  __syncthreads();

  unsigned bar_target = 0;
  for (int t = 0; t < T_; ++t){
    const int cur = t & 1, nxt = cur ^ 1;

    // ---------------- phase A: gates GEMM + LSTM cell ----------------
    if (actA){
      if (tid == 0) g_pack[nxt][cta] = 0ull;              // clear next argmax slot
      if (tid < B_){
        unsigned long long p = __ldcg(&g_pack[cur][tid]);
        ((int*)&sm[STOK])[tid] = (VOCAB_-1) - (int)(unsigned)(p & 0xffffffffull);
      }
      __syncthreads();
      float acc[4][2];
      for (int i=0;i<4;++i){
        int tok = ((int*)&sm[STOK])[r0+i];
        acc[i][0] = basev[i][0] + __ldg(&g_E[(size_t)tok*NG_ + gc0]);
        acc[i][1] = basev[i][1] + __ldg(&g_E[(size_t)tok*NG_ + gc1]);
      }
      const float* hsrc = g_h[cur];
      for (int kc = 0; kc < HID_; kc += 64){
        for (int p = 0; p < 8; ++p){
          int lin = tid + p*NTHR; int r = lin >> 4, kq = lin & 15;
          float4 v = __ldcg((const float4*)(hsrc + (size_t)r*HID_ + kc + 4*kq));
          *(float4*)&sm[SH_S + r*68 + 4*kq] = v;
        }
        __syncthreads();
#pragma unroll
        for (int k4 = 0; k4 < 16; ++k4){
          int kl = 4*k4;
          float4 w0 = *(const float4*)&sm[SW_HH + (2*tx)*520 + kc + kl];
          float4 w1 = *(const float4*)&sm[SW_HH + (2*tx+1)*520 + kc + kl];
#pragma unroll
          for (int i=0;i<4;++i){
            float4 h4 = *(const float4*)&sm[SH_S + (r0+i)*68 + kl];
            DOT4(acc[i][0], h4, w0); DOT4(acc[i][1], h4, w1);
          }
        }
        __syncthreads();
      }
      for (int i=0;i<4;++i){
        sm[SG_S + (2*tx)*132 + r0+i]   = acc[i][0];
        sm[SG_S + (2*tx+1)*132 + r0+i] = acc[i][1];
      }
      __syncthreads();
      for (int q = 0; q < 2; ++q){
        int p = tid*2 + q;            // (r,u) pair
        int r = p >> 2, u = p & 3;
        float ig = sm[SG_S + ( 0+u)*132 + r];
        float fg = sm[SG_S + ( 4+u)*132 + r];
        float gg = sm[SG_S + ( 8+u)*132 + r];
        float og = sm[SG_S + (12+u)*132 + r];
        ig = 1.f/(1.f + expf(-ig));
        fg = 1.f/(1.f + expf(-fg));
        gg = tanhf(gg);
        og = 1.f/(1.f + expf(-og));
        float cn = fmaf(fg, sm[SC_S + u*128 + r], ig*gg);
        sm[SC_S + u*128 + r] = cn;
        g_h[nxt][(size_t)r*HID_ + 4*cta + u] = og * tanhf(cn);
      }
    }
    bar_target += GRID_; gbar(bar_target);

    // ---------------- phase B: logits GEMM + argmax ------------------
    if (actB){
      float acc[4];
      for (int i=0;i<4;++i) acc[i] = boutv;
      const float* hsrc = g_h[nxt];
      for (int kc = 0; kc < HID_; kc += 64){
        for (int p = 0; p < 8; ++p){
          int lin = tid + p*NTHR; int r = lin >> 4, kq = lin & 15;
          float4 v = __ldcg((const float4*)(hsrc + (size_t)r*HID_ + kc + 4*kq));
          *(float4*)&sm[SH_S + r*68 + 4*kq] = v;
        }
        __syncthreads();
#pragma unroll
        for (int k4 = 0; k4 < 16; ++k4){
          int kl = 4*k4;
          float4 w = *(const float4*)&sm[SW_OUT + tx*520 + kc + kl];
#pragma unroll
          for (int i=0;i<4;++i){
            float4 h4 = *(const float4*)&sm[SH_S + (r0+i)*68 + kl];
            DOT4(acc[i], h4, w);
          }
        }
        __syncthreads();
      }
      unsigned long long best[4];
      for (int i=0;i<4;++i){
        int r = r0 + i;
        out[((size_t)r*T_ + t)*VOCAB_ + colB] = acc[i];
        best[i] = ((unsigned long long)fkey(acc[i]) << 32)
                | (unsigned)(VOCAB_-1 - colB);
      }
#pragma unroll
      for (int s = 1; s < 8; s <<= 1){
        for (int i=0;i<4;++i){
          unsigned long long o = __shfl_xor_sync(0xffffffffu, best[i], s);
          if (o > best[i]) best[i] = o;
        }
      }
      if (tx == 0)
        for (int i=0;i<4;++i) atomicMax(&g_pack[nxt][r0+i], best[i]);
    }
    bar_target += GRID_; gbar(bar_target);
  }

  // final h, c
  if (actA){
    for (int q = 0; q < 2; ++q){
      int p = tid*2 + q; int r = p >> 2, u = p & 3;
      int j = 4*cta + u;
      out[OUT_C + (size_t)r*HID_ + j] = sm[SC_S + u*128 + r];
      out[OUT_H + (size_t)r*HID_ + j] = __ldcg(&g_h[0][(size_t)r*HID_ + j]);
    }
  }
}

// ---------------------------------------------------------------- launch
extern "C" void kernel_launch(void* const* d_in, const int* in_sizes, int n_in,
                              void* d_out, int out_size){
  const float* ctx  = (const float*)d_in[0];
  const float* emb  = (const float*)d_in[1];
  const float* Wih  = (const float*)d_in[2];
  const float* bih  = (const float*)d_in[3];
  const float* Whh  = (const float*)d_in[4];
  const float* bhh  = (const float*)d_in[5];
  const float* Wout = (const float*)d_in[6];
  const float* bout = (const float*)d_in[7];
  const int*   sid  = (const int*)d_in[8];
  float* out = (float*)d_out;

  cudaFuncSetAttribute(k_persist, cudaFuncAttributeMaxDynamicSharedMemorySize,
                       SM_WORDS * 4);

  dim3 gE(32, 16);
  k_E<<<gE, 256>>>(emb, Wih);
  k_base<<<128, 256>>>(Wih, bih, bhh, ctx);
  k_init<<<256, 256>>>(ctx, sid);
  k_persist<<<GRID_, NTHR, SM_WORDS * 4>>>(Whh, Wout, bout, out);
}

// round 3
// speedup vs baseline: 2.0198x; 2.0198x over previous
#include <cuda_runtime.h>
#include <math.h>

#define B_     128
#define HID_   512
#define NG_    2048
#define VOCAB_ 1000
#define T_     256
#define GRID_  148
#define NTHR   256
#define NC_    21          // real virtual-cols per CTA (148*21 = 3108 >= 3048)
#define NCP_   24          // padded tile cols
#define VTOT_  3048        // 2048 gate cols + 1000 vocab cols

#define OUT_H  (B_*T_*VOCAB_)
#define OUT_C  (OUT_H + B_*HID_)

// ---------------- device scratch ----------------
__device__ float g_E2[VOCAB_*NG_];        // [v][u][4 gates]  (i,f,g,o per unit)
__device__ float g_base[NG_*B_];          // col-major [gatecol][row] : ctx part + b_ih + b_hh
__device__ float g_G[2][NG_*B_];          // col-major per-kg partial gates (incl base in kg0)
__device__ float g_h[2][B_*HID_];         // double-buffered hidden, row-major [r][u]
__device__ unsigned long long g_pack[2][B_];
__device__ unsigned g_bar;

__device__ __forceinline__ unsigned fkey(float x){
  unsigned u = __float_as_uint(x);
  return (u & 0x80000000u) ? ~u : (u | 0x80000000u);
}
#define DOT4(acc, a, b) acc = fmaf((a).x,(b).x, fmaf((a).y,(b).y, fmaf((a).z,(b).z, fmaf((a).w,(b).w,(acc)))))

// ---------------- prologue 1: E2[v][u][g] = sum_k emb[v][k]*Wih[g*512+u][512+k]
__global__ void __launch_bounds__(256) k_E(const float* __restrict__ emb,
                                           const float* __restrict__ Wih){
  __shared__ float As[16*68], Bs[16*68];
  const int tid = threadIdx.x;
  const int tx = tid & 15, ty = tid >> 4;
  const int c0 = blockIdx.x * 64, v0 = blockIdx.y * 64;
  float acc[4][4];
#pragma unroll
  for (int i=0;i<4;++i)
#pragma unroll
    for (int j=0;j<4;++j) acc[i][j] = 0.f;

  const int rr = tid >> 2, kq = tid & 3;
  for (int kc = 0; kc < 512; kc += 16){
    int v = v0 + rr; if (v >= VOCAB_) v = VOCAB_ - 1;
    float4 a = __ldg((const float4*)(emb + (size_t)v*512 + kc + 4*kq));
    As[(4*kq+0)*68 + rr] = a.x; As[(4*kq+1)*68 + rr] = a.y;
    As[(4*kq+2)*68 + rr] = a.z; As[(4*kq+3)*68 + rr] = a.w;
    int g = c0 + rr;
    float4 b = __ldg((const float4*)(Wih + (size_t)g*1024 + 512 + kc + 4*kq));
    Bs[(4*kq+0)*68 + rr] = b.x; Bs[(4*kq+1)*68 + rr] = b.y;
    Bs[(4*kq+2)*68 + rr] = b.z; Bs[(4*kq+3)*68 + rr] = b.w;
    __syncthreads();
#pragma unroll
    for (int k = 0; k < 16; ++k){
      float4 av = *(const float4*)&As[k*68 + ty*4];
      float4 bv = *(const float4*)&Bs[k*68 + tx*4];
      float ai[4] = {av.x, av.y, av.z, av.w};
      float bj[4] = {bv.x, bv.y, bv.z, bv.w};
#pragma unroll
      for (int i=0;i<4;++i)
#pragma unroll
        for (int j=0;j<4;++j) acc[i][j] = fmaf(ai[i], bj[j], acc[i][j]);
    }
    __syncthreads();
  }
  for (int i=0;i<4;++i){
    int v = v0 + ty*4 + i;
    if (v < VOCAB_)
      for (int j=0;j<4;++j){
        int c = c0 + tx*4 + j;                       // 0..2047
        g_E2[((size_t)v*512 + (c & 511))*4 + (c >> 9)] = acc[i][j];
      }
  }
}

// ---------------- prologue 2: g_base[gcol][r] = ctx@Wih_ctx^T + b_ih + b_hh
__global__ void __launch_bounds__(256) k_base(const float* __restrict__ Wih,
                                              const float* __restrict__ bih,
                                              const float* __restrict__ bhh,
                                              const float* __restrict__ ctx){
  __shared__ float xs[128*68], wsm[16*68];
  const int tid = threadIdx.x, blk = blockIdx.x;   // 128 blocks x 16 cols
  const int tx = tid & 7, ty = tid >> 3, r0 = ty*4;
  const int gc0 = blk*16 + 2*tx, gc1 = gc0 + 1;
  float acc[4][2];
#pragma unroll
  for (int i=0;i<4;++i){ acc[i][0]=0.f; acc[i][1]=0.f; }

  for (int kc = 0; kc < 512; kc += 64){
    for (int p = 0; p < 8; ++p){
      int lin = tid + p*256; int r = lin >> 4, kq2 = lin & 15;
      *(float4*)&xs[r*68 + 4*kq2] = __ldg((const float4*)(ctx + (size_t)r*512 + kc + 4*kq2));
    }
    { int cc = tid >> 4, kq2 = tid & 15;
      *(float4*)&wsm[cc*68 + 4*kq2] =
        __ldg((const float4*)(Wih + (size_t)(blk*16+cc)*1024 + kc + 4*kq2)); }
    __syncthreads();
#pragma unroll
    for (int k4 = 0; k4 < 16; ++k4){
      int kl = 4*k4;
      float4 w0 = *(const float4*)&wsm[(2*tx)*68 + kl];
      float4 w1 = *(const float4*)&wsm[(2*tx+1)*68 + kl];
#pragma unroll
      for (int i=0;i<4;++i){
        float4 h4 = *(const float4*)&xs[(r0+i)*68 + kl];
        DOT4(acc[i][0], h4, w0); DOT4(acc[i][1], h4, w1);
      }
    }
    __syncthreads();
  }
  float bb0 = __ldg(bih+gc0) + __ldg(bhh+gc0);
  float bb1 = __ldg(bih+gc1) + __ldg(bhh+gc1);
  for (int i=0;i<4;++i){
    g_base[(size_t)gc0*B_ + r0+i] = acc[i][0] + bb0;
    g_base[(size_t)gc1*B_ + r0+i] = acc[i][1] + bb1;
  }
}

// ---------------- prologue 3
__global__ void k_init(const float* __restrict__ ctx, const int* __restrict__ sid){
  int idx = blockIdx.x*blockDim.x + threadIdx.x;
  if (idx < B_*HID_) g_h[0][idx] = ctx[idx];
  if (idx < B_){
    g_pack[0][idx] = (unsigned long long)(unsigned)((VOCAB_-1) - *sid);
    g_pack[1][idx] = 0ull;
  }
  if (idx == 0) g_bar = 0u;
}

// ---------------- grid barrier
__device__ __forceinline__ void gbar(unsigned target){
  __syncthreads();
  if (threadIdx.x == 0){
    __threadfence();
    atomicAdd(&g_bar, 1u);
    while (*(volatile unsigned*)&g_bar < target) { }
    __threadfence();
  }
  __syncthreads();
}

// ---------------- persistent kernel ------------------------------------
// smem word offsets
#define SW_   0                      // ws  [24][516]
#define SH_   (SW_ + NCP_*516)       // hs  [2][128][64]
#define SL_   (SH_ + 2*128*64)       // Ls  [24][132]
#define SB_   (SL_ + NCP_*132)       // bs  [24][132]
#define SMW_  (SB_ + NCP_*132)       // 35104 words = 140416 B

__global__ void __launch_bounds__(NTHR, 1) k_persist(const float* __restrict__ Whh,
                                                     const float* __restrict__ Wout,
                                                     const float* __restrict__ bout,
                                                     float* __restrict__ out){
  extern __shared__ float sm[];
  float* ws = sm + SW_;
  float* hs = sm + SH_;
  float* Ls = sm + SL_;
  float* bs = sm + SB_;

  const int cta = blockIdx.x, tid = threadIdx.x;
  const int kg = tid >> 7, t = tid & 127;
  const int cg = t & 7, rg = t >> 3;
  const int r0 = rg*8, c0 = cg*3;
  const int vbase = cta*NC_;

  // ---- stage weights + base/bias slices (resident for whole run)
  for (int c = 0; c < NCP_; ++c){
    int vcol = vbase + c;
    const float* src = 0;
    if (vcol < NG_) src = Whh + (size_t)vcol*HID_;
    else if (vcol < VTOT_) src = Wout + (size_t)(vcol-NG_)*HID_;
    for (int k4 = tid; k4 < 128; k4 += NTHR){
      float4 v = src ? __ldg((const float4*)(src + 4*k4)) : make_float4(0.f,0.f,0.f,0.f);
      *(float4*)&ws[c*516 + 4*k4] = v;
    }
    for (int r = tid; r < B_; r += NTHR){
      float v = 0.f;
      if (vcol < NG_)       v = __ldg(&g_base[(size_t)vcol*B_ + r]);
      else if (vcol < VTOT_) v = __ldg(&bout[vcol-NG_]);
      bs[c*132 + r] = v;
    }
  }
  __syncthreads();

  // cell state lives in registers of the Y-phase owning thread
  float creg0 = 0.f, creg1 = 0.f;
  const int yidx0 = cta*NTHR + tid;
  const int yidx1 = yidx0 + GRID_*NTHR;

  unsigned bt = 0;
  for (int m = 0; m <= T_; ++m){
    const int cur = m & 1;
    const float* hsrc = g_h[cur];

    // ---------------- phase X: unified GEMM over 24 cols -------------
    float acc[8][3];
    if (kg == 0){
#pragma unroll
      for (int j = 0; j < 3; ++j){
        float4 b0 = *(const float4*)&bs[(c0+j)*132 + r0];
        float4 b1 = *(const float4*)&bs[(c0+j)*132 + r0 + 4];
        acc[0][j]=b0.x; acc[1][j]=b0.y; acc[2][j]=b0.z; acc[3][j]=b0.w;
        acc[4][j]=b1.x; acc[5][j]=b1.y; acc[6][j]=b1.z; acc[7][j]=b1.w;
      }
    } else {
#pragma unroll
      for (int i=0;i<8;++i)
#pragma unroll
        for (int j=0;j<3;++j) acc[i][j] = 0.f;
    }

    for (int ch = 0; ch < 4; ++ch){
      // stage 128x64 h chunk for each kg half
#pragma unroll
      for (int p = 0; p < 16; ++p){
        int f = tid + p*NTHR;
        int kgl = f >> 11, row = (f >> 4) & 127, kq = f & 15;
        *(float4*)&hs[kgl*8192 + row*64 + kq*4] =
          __ldcg((const float4*)(hsrc + (size_t)row*HID_ + kgl*256 + ch*64 + kq*4));
      }
      __syncthreads();
      const float* hb = &hs[kg*8192];
      const float* wb = &ws[kg*256 + ch*64];
#pragma unroll 4
      for (int k4 = 0; k4 < 16; ++k4){
        int kl = 4*k4;
        float4 w4[3], h4[8];
#pragma unroll
        for (int j=0;j<3;++j) w4[j] = *(const float4*)&wb[(c0+j)*516 + kl];
#pragma unroll
        for (int i=0;i<8;++i) h4[i] = *(const float4*)&hb[(r0+i)*64 + kl];
#pragma unroll
        for (int i=0;i<8;++i)
#pragma unroll
          for (int j=0;j<3;++j) DOT4(acc[i][j], h4[i], w4[j]);
      }
      __syncthreads();
    }

    // ---- gate columns -> g_G (col-major, per-kg partials)
    if (m < T_){
#pragma unroll
      for (int j = 0; j < 3; ++j){
        int vcol = vbase + c0 + j;
        if (vcol < NG_){
          float4 lo = make_float4(acc[0][j],acc[1][j],acc[2][j],acc[3][j]);
          float4 hi = make_float4(acc[4][j],acc[5][j],acc[6][j],acc[7][j]);
          *(float4*)&g_G[kg][(size_t)vcol*B_ + r0]     = lo;
          *(float4*)&g_G[kg][(size_t)vcol*B_ + r0 + 4] = hi;
        }
      }
    }
    // ---- vocab columns: combine kg partials, emit logits + argmax
    if (kg == 1){
#pragma unroll
      for (int j = 0; j < 3; ++j){
        int vcol = vbase + c0 + j;
        if (vcol >= NG_ && vcol < VTOT_){
          float4 lo = make_float4(acc[0][j],acc[1][j],acc[2][j],acc[3][j]);
          float4 hi = make_float4(acc[4][j],acc[5][j],acc[6][j],acc[7][j]);
          *(float4*)&Ls[(c0+j)*132 + r0]     = lo;
          *(float4*)&Ls[(c0+j)*132 + r0 + 4] = hi;
        }
      }
    }
    __syncthreads();
    if (kg == 0 && m >= 1){
      unsigned long long best[8];
#pragma unroll
      for (int i=0;i<8;++i) best[i] = 0ull;
#pragma unroll
      for (int j = 0; j < 3; ++j){
        int vcol = vbase + c0 + j;
        if (vcol >= NG_ && vcol < VTOT_){
          int v = vcol - NG_;
#pragma unroll
          for (int i=0;i<8;++i){
            float tot = acc[i][j] + Ls[(c0+j)*132 + r0 + i];
            out[((size_t)(r0+i)*T_ + (m-1))*VOCAB_ + v] = tot;
            if (m < T_ + 1){
              unsigned long long pk = ((unsigned long long)fkey(tot) << 32)
                                    | (unsigned)(VOCAB_-1 - v);
              if (pk > best[i]) best[i] = pk;
            }
          }
        }
      }
      if (m < T_){
#pragma unroll
        for (int s = 1; s < 8; s <<= 1){
#pragma unroll
          for (int i=0;i<8;++i){
            unsigned long long o = __shfl_xor_sync(0xffffffffu, best[i], s);
            if (o > best[i]) best[i] = o;
          }
        }
        if (cg == 0){
#pragma unroll
          for (int i=0;i<8;++i)
            if (best[i]) atomicMax(&g_pack[cur][r0+i], best[i]);
        }
      }
    }

    if (m == T_) break;          // final logits emitted; no cell update needed
    bt += GRID_; gbar(bt);

    // ---------------- phase Y: E-gather + LSTM cell update -----------
    const int nxt = cur ^ 1;
    float* hdst = g_h[nxt];
#pragma unroll
    for (int q = 0; q < 2; ++q){
      int idx = q ? yidx1 : yidx0;
      if (idx < B_*HID_){
        int r = idx & 127, u = idx >> 7;
        unsigned long long p = __ldcg(&g_pack[cur][r]);
        int tok = (VOCAB_-1) - (int)(unsigned)(p & 0xffffffffull);
        float4 ev = __ldg((const float4*)&g_E2[((size_t)tok*HID_ + u)*4]);
        float gi = __ldcg(&g_G[0][(size_t)u*B_ + r])        + __ldcg(&g_G[1][(size_t)u*B_ + r])        + ev.x;
        float gf = __ldcg(&g_G[0][(size_t)(512+u)*B_ + r])  + __ldcg(&g_G[1][(size_t)(512+u)*B_ + r])  + ev.y;
        float gg = __ldcg(&g_G[0][(size_t)(1024+u)*B_ + r]) + __ldcg(&g_G[1][(size_t)(1024+u)*B_ + r]) + ev.z;
        float go = __ldcg(&g_G[0][(size_t)(1536+u)*B_ + r]) + __ldcg(&g_G[1][(size_t)(1536+u)*B_ + r]) + ev.w;
        gi = 1.f/(1.f + expf(-gi));
        gf = 1.f/(1.f + expf(-gf));
        gg = tanhf(gg);
        go = 1.f/(1.f + expf(-go));
        float cold = q ? creg1 : creg0;
        float cn = fmaf(gf, cold, gi*gg);
        if (q) creg1 = cn; else creg0 = cn;
        float hn = go * tanhf(cn);
        hdst[(size_t)r*HID_ + u] = hn;
        if (m == T_-1){
          out[OUT_H + (size_t)r*HID_ + u] = hn;
          out[OUT_C + (size_t)r*HID_ + u] = cn;
        }
      }
    }
    if (yidx0 < B_) g_pack[nxt][yidx0] = 0ull;   // clear next argmax slot
    bt += GRID_; gbar(bt);
  }
}

// ---------------- launch -----------------------------------------------
extern "C" void kernel_launch(void* const* d_in, const int* in_sizes, int n_in,
                              void* d_out, int out_size){
  const float* ctx  = (const float*)d_in[0];
  const float* emb  = (const float*)d_in[1];
  const float* Wih  = (const float*)d_in[2];
  const float* bih  = (const float*)d_in[3];
  const float* Whh  = (const float*)d_in[4];
  const float* bhh  = (const float*)d_in[5];
  const float* Wout = (const float*)d_in[6];
  const float* bout = (const float*)d_in[7];
  const int*   sid  = (const int*)d_in[8];
  float* out = (float*)d_out;

  cudaFuncSetAttribute(k_persist, cudaFuncAttributeMaxDynamicSharedMemorySize,
                       SMW_ * 4);

  dim3 gE(32, 16);
  k_E<<<gE, 256>>>(emb, Wih);
  k_base<<<128, 256>>>(Wih, bih, bhh, ctx);
  k_init<<<256, 256>>>(ctx, sid);
  k_persist<<<GRID_, NTHR, SMW_ * 4>>>(Whh, Wout, bout, out);
}

// round 5
// speedup vs baseline: 2.6336x; 1.3039x over previous
#include <cuda_runtime.h>
#include <math.h>
#include <stdint.h>

#define B_     128
#define HID_   512
#define NG_    2048
#define VOCAB_ 1000
#define VTOT_  3048
#define ROWS_  3072
#define T_     256
#define GRID_  148
#define NTHR   256
#define XCTAS  128           // 32 M-tiles (96 rows) x 4 K-splits

#define OUT_H  (B_*T_*VOCAB_)
#define OUT_C  (OUT_H + B_*HID_)

// ---------------- device scratch ----------------
__device__ __align__(16) float g_E2[VOCAB_*NG_];     // [v][u][4]: i,f,g,o
__device__ __align__(16) float g_base[NG_*B_];       // col-major [gatecol][r]
__device__ __align__(16) float g_hhi[B_*HID_];       // tf32-hi of h
__device__ __align__(16) float g_hlo[B_*HID_];       // tf32-lo of h
__device__ __align__(16) float g_part[4*ROWS_*B_];   // [k][row][r]
__device__ unsigned long long g_pack[2][B_];
__device__ unsigned g_bar;

__device__ __forceinline__ float tf32_rd(float x){
  uint32_t u; asm("cvt.rna.tf32.f32 %0, %1;" : "=r"(u) : "f"(x));
  return __uint_as_float(u);
}
__device__ __forceinline__ unsigned fkey(float x){
  unsigned u = __float_as_uint(x);
  return (u & 0x80000000u) ? ~u : (u | 0x80000000u);
}
__device__ __forceinline__ void mma_tf32(float* d, const uint32_t* a, const uint32_t* b){
  asm volatile("mma.sync.aligned.m16n8k8.row.col.f32.tf32.tf32.f32 "
    "{%0,%1,%2,%3}, {%4,%5,%6,%7}, {%8,%9}, {%0,%1,%2,%3};"
    : "+f"(d[0]), "+f"(d[1]), "+f"(d[2]), "+f"(d[3])
    : "r"(a[0]), "r"(a[1]), "r"(a[2]), "r"(a[3]), "r"(b[0]), "r"(b[1]));
}
#define DOT4(acc, a, b) acc = fmaf((a).x,(b).x, fmaf((a).y,(b).y, fmaf((a).z,(b).z, fmaf((a).w,(b).w,(acc)))))

// ---------------- prologue 1: E2 = embed @ Wih_emb^T ----------------
__global__ void __launch_bounds__(256) k_E(const float* __restrict__ emb,
                                           const float* __restrict__ Wih){
  __shared__ float As[16*68], Bs[16*68];
  const int tid = threadIdx.x;
  const int tx = tid & 15, ty = tid >> 4;
  const int c0 = blockIdx.x * 64, v0 = blockIdx.y * 64;
  float acc[4][4];
#pragma unroll
  for (int i=0;i<4;++i)
#pragma unroll
    for (int j=0;j<4;++j) acc[i][j] = 0.f;

  const int rr = tid >> 2, kq = tid & 3;
  for (int kc = 0; kc < 512; kc += 16){
    int v = v0 + rr; if (v >= VOCAB_) v = VOCAB_ - 1;
    float4 a = __ldg((const float4*)(emb + (size_t)v*512 + kc + 4*kq));
    As[(4*kq+0)*68 + rr] = a.x; As[(4*kq+1)*68 + rr] = a.y;
    As[(4*kq+2)*68 + rr] = a.z; As[(4*kq+3)*68 + rr] = a.w;
    int g = c0 + rr;
    float4 b = __ldg((const float4*)(Wih + (size_t)g*1024 + 512 + kc + 4*kq));
    Bs[(4*kq+0)*68 + rr] = b.x; Bs[(4*kq+1)*68 + rr] = b.y;
    Bs[(4*kq+2)*68 + rr] = b.z; Bs[(4*kq+3)*68 + rr] = b.w;
    __syncthreads();
#pragma unroll
    for (int k = 0; k < 16; ++k){
      float4 av = *(const float4*)&As[k*68 + ty*4];
      float4 bv = *(const float4*)&Bs[k*68 + tx*4];
      float ai[4] = {av.x, av.y, av.z, av.w};
      float bj[4] = {bv.x, bv.y, bv.z, bv.w};
#pragma unroll
      for (int i=0;i<4;++i)
#pragma unroll
        for (int j=0;j<4;++j) acc[i][j] = fmaf(ai[i], bj[j], acc[i][j]);
    }
    __syncthreads();
  }
  for (int i=0;i<4;++i){
    int v = v0 + ty*4 + i;
    if (v < VOCAB_)
      for (int j=0;j<4;++j){
        int c = c0 + tx*4 + j;
        g_E2[((size_t)v*512 + (c & 511))*4 + (c >> 9)] = acc[i][j];
      }
  }
}

// ---------------- prologue 2: g_base (exact fp32) ----------------
__global__ void __launch_bounds__(256) k_base(const float* __restrict__ Wih,
                                              const float* __restrict__ bih,
                                              const float* __restrict__ bhh,
                                              const float* __restrict__ ctx){
  __shared__ float xs[128*68], wsm[16*68];
  const int tid = threadIdx.x, blk = blockIdx.x;
  const int tx = tid & 7, ty = tid >> 3, r0 = ty*4;
  const int gc0 = blk*16 + 2*tx, gc1 = gc0 + 1;
  float acc[4][2];
#pragma unroll
  for (int i=0;i<4;++i){ acc[i][0]=0.f; acc[i][1]=0.f; }

  for (int kc = 0; kc < 512; kc += 64){
    for (int p = 0; p < 8; ++p){
      int lin = tid + p*256; int r = lin >> 4, kq2 = lin & 15;
      *(float4*)&xs[r*68 + 4*kq2] = __ldg((const float4*)(ctx + (size_t)r*512 + kc + 4*kq2));
    }
    { int cc = tid >> 4, kq2 = tid & 15;
      *(float4*)&wsm[cc*68 + 4*kq2] =
        __ldg((const float4*)(Wih + (size_t)(blk*16+cc)*1024 + kc + 4*kq2)); }
    __syncthreads();
#pragma unroll
    for (int k4 = 0; k4 < 16; ++k4){
      int kl = 4*k4;
      float4 w0 = *(const float4*)&wsm[(2*tx)*68 + kl];
      float4 w1 = *(const float4*)&wsm[(2*tx+1)*68 + kl];
#pragma unroll
      for (int i=0;i<4;++i){
        float4 h4 = *(const float4*)&xs[(r0+i)*68 + kl];
        DOT4(acc[i][0], h4, w0); DOT4(acc[i][1], h4, w1);
      }
    }
    __syncthreads();
  }
  float bb0 = __ldg(bih+gc0) + __ldg(bhh+gc0);
  float bb1 = __ldg(bih+gc1) + __ldg(bhh+gc1);
  for (int i=0;i<4;++i){
    g_base[(size_t)gc0*B_ + r0+i] = acc[i][0] + bb0;
    g_base[(size_t)gc1*B_ + r0+i] = acc[i][1] + bb1;
  }
}

// ---------------- prologue 3 ----------------
__global__ void k_init(const float* __restrict__ ctx, const int* __restrict__ sid){
  int idx = blockIdx.x*blockDim.x + threadIdx.x;
  if (idx < B_*HID_){
    float x = ctx[idx];
    float hi = tf32_rd(x);
    g_hhi[idx] = hi;
    g_hlo[idx] = tf32_rd(x - hi);
  }
  if (idx < B_){
    g_pack[0][idx] = (unsigned long long)(unsigned)((VOCAB_-1) - *sid);
    g_pack[1][idx] = 0ull;
  }
  if (idx == 0) g_bar = 0u;
}

// ---------------- grid barrier ----------------
__device__ __forceinline__ void gbar(unsigned target){
  __syncthreads();
  if (threadIdx.x == 0){
    __threadfence();
    atomicAdd(&g_bar, 1u);
    while (*(volatile unsigned*)&g_bar < target) { }
    __threadfence();
  }
  __syncthreads();
}

// ---------------- persistent kernel ----------------
// smem float offsets
#define SA_H   0                 // A hi frag-packed: 96*128 = 12288
#define SA_L   12288             // A lo
#define SB_H   24576             // B hi tile [128][68] = 8704
#define SB_L   33280             // B lo tile
#define S_TOK  41984             // 128 ints
#define S_LS   42112             // 8*128 floats
#define SMW_   43136             // 172544 bytes

__global__ void __launch_bounds__(NTHR, 1)
k_persist(const float* __restrict__ Whh, const float* __restrict__ Wout,
          const float* __restrict__ bout, float* __restrict__ out){
  extern __shared__ float sm[];
  float* Ah = sm + SA_H;
  float* Al = sm + SA_L;
  float* Bh = sm + SB_H;
  float* Bl = sm + SB_L;
  int*   toks = (int*)(sm + S_TOK);
  float* Ls = sm + S_LS;

  const int cta = blockIdx.x, tid = threadIdx.x;
  const int wid = tid >> 5, lane = tid & 31;
  const bool isX = (cta < XCTAS);
  const int mtile = cta >> 2, kidx = cta & 3, kbase = kidx*128;
  const int wm = wid >> 2, wn = wid & 3;          // warp tile 48M x 32N

  // ---- stage A (weights hi/lo, fragment-packed) once ----
  if (isX){
    for (int lin = tid; lin < 3072; lin += NTHR){
      int ml = lin >> 5, q = lin & 31;            // row-in-tile, float4-in-K
      int gm = mtile*96 + ml;
      float4 w = make_float4(0.f,0.f,0.f,0.f);
      if (gm < NG_)        w = __ldg((const float4*)(Whh  + (size_t)gm*HID_ + kbase + q*4));
      else if (gm < VTOT_) w = __ldg((const float4*)(Wout + (size_t)(gm-NG_)*HID_ + kbase + q*4));
      int f = (ml >> 4)*16 + (q >> 1);
      int ofs = f*128 + (ml & 7)*16 + ((ml >> 3) & 1) + 2*(q & 1);
      float hi;
      hi = tf32_rd(w.x); Ah[ofs+ 0] = hi; Al[ofs+ 0] = tf32_rd(w.x - hi);
      hi = tf32_rd(w.y); Ah[ofs+ 4] = hi; Al[ofs+ 4] = tf32_rd(w.y - hi);
      hi = tf32_rd(w.z); Ah[ofs+ 8] = hi; Al[ofs+ 8] = tf32_rd(w.z - hi);
      hi = tf32_rd(w.w); Ah[ofs+12] = hi; Al[ofs+12] = tf32_rd(w.w - hi);
    }
  }
  __syncthreads();

  float cr0 = 0.f, cr1 = 0.f;
  const int yi0 = cta*NTHR + tid;
  const int yi1 = yi0 + GRID_*NTHR;

  unsigned bt = 0;
  for (int m = 0; m <= T_; ++m){
    // ================ phase X: 3xTF32 mma.sync ================
    if (isX){
      float acc[12][4];
#pragma unroll
      for (int i=0;i<12;++i)
#pragma unroll
        for (int j=0;j<4;++j) acc[i][j] = 0.f;

      for (int ch = 0; ch < 2; ++ch){
        // stage B chunk (64 K-floats, hi+lo), conflict-free
        for (int lin = tid; lin < 2048; lin += NTHR){
          int r = lin >> 4, q = lin & 15;
          float4 h = __ldcg((const float4*)(g_hhi + (size_t)r*HID_ + kbase + ch*64 + q*4));
          float4 l = __ldcg((const float4*)(g_hlo + (size_t)r*HID_ + kbase + ch*64 + q*4));
          *(float4*)&Bh[r*68 + q*4] = h;
          *(float4*)&Bl[r*68 + q*4] = l;
        }
        __syncthreads();
#pragma unroll 2
        for (int ks = 0; ks < 8; ++ks){
          uint32_t bh[4][2], bl[4][2];
          int kk = ks*8 + (lane & 3);
#pragma unroll
          for (int ni = 0; ni < 4; ++ni){
            int n = wn*32 + ni*8 + (lane >> 2);
            bh[ni][0] = __float_as_uint(Bh[n*68 + kk]);
            bh[ni][1] = __float_as_uint(Bh[n*68 + kk + 4]);
            bl[ni][0] = __float_as_uint(Bl[n*68 + kk]);
            bl[ni][1] = __float_as_uint(Bl[n*68 + kk + 4]);
          }
#pragma unroll
          for (int mi = 0; mi < 3; ++mi){
            int f = (wm*3 + mi)*16 + ch*8 + ks;
            uint4 ahv = *(const uint4*)&Ah[(f*32 + lane)*4];
            uint4 alv = *(const uint4*)&Al[(f*32 + lane)*4];
            const uint32_t* ah = (const uint32_t*)&ahv;
            const uint32_t* al = (const uint32_t*)&alv;
#pragma unroll
            for (int ni = 0; ni < 4; ++ni){
              mma_tf32(acc[mi*4+ni], ah, bh[ni]);
              mma_tf32(acc[mi*4+ni], ah, bl[ni]);
              mma_tf32(acc[mi*4+ni], al, bh[ni]);
            }
          }
        }
        __syncthreads();
      }
      // store D partials to g_part[kidx][row][r]
#pragma unroll
      for (int mi = 0; mi < 3; ++mi){
#pragma unroll
        for (int ni = 0; ni < 4; ++ni){
          int row0 = mtile*96 + wm*48 + mi*16 + (lane >> 2);
          int col = wn*32 + ni*8 + (lane & 3)*2;
          float* dst = g_part + ((size_t)kidx*ROWS_ + row0)*B_ + col;
          float2 v0 = make_float2(acc[mi*4+ni][0], acc[mi*4+ni][1]);
          float2 v1 = make_float2(acc[mi*4+ni][2], acc[mi*4+ni][3]);
          *(float2*)dst = v0;
          *(float2*)(dst + 8*B_) = v1;
        }
      }
    }
    bt += GRID_; gbar(bt);

    // ================ phase Yv: vocab reduce + argmax ================
    if (m >= 1){
      const int v0 = cta*7;
      if (wid < 7){
        int v = v0 + wid;
        if (v < VOCAB_){
          float bo = __ldg(bout + v);
          const float* p = g_part + (size_t)(NG_ + v)*B_;
#pragma unroll
          for (int rq = 0; rq < 4; ++rq){
            int r = rq*32 + lane;
            float sum = bo + __ldcg(p + r)
                      + __ldcg(p + (size_t)ROWS_*B_ + r)
                      + __ldcg(p + (size_t)2*ROWS_*B_ + r)
                      + __ldcg(p + (size_t)3*ROWS_*B_ + r);
            Ls[wid*128 + r] = sum;
          }
        }
      }
      __syncthreads();
      for (int it = tid; it < 128*8; it += NTHR){
        int r = it >> 3, vl = it & 7;
        int v = v0 + vl;
        if (vl < 7 && v < VOCAB_)
          out[((size_t)r*T_ + (m-1))*VOCAB_ + v] = Ls[vl*128 + r];
      }
      if (m < T_ && tid < 128){
        int r = tid;
        unsigned long long best = 0ull;
        for (int vl = 0; vl < 7; ++vl){
          int v = v0 + vl;
          if (v < VOCAB_){
            unsigned long long pk = ((unsigned long long)fkey(Ls[vl*128 + r]) << 32)
                                  | (unsigned)(VOCAB_-1 - v);
            if (pk > best) best = pk;
          }
        }
        if (best) atomicMax(&g_pack[m & 1][r], best);
      }
      __syncthreads();
    }
    if (m == T_) break;
    bt += GRID_; gbar(bt);

    // ================ phase Yc: E-gather + LSTM cell ================
    {
      if (tid < B_){
        unsigned long long p = __ldcg(&g_pack[m & 1][tid]);
        toks[tid] = (VOCAB_-1) - (int)(unsigned)(p & 0xffffffffull);
      }
      __syncthreads();
#pragma unroll
      for (int q = 0; q < 2; ++q){
        int idx = q ? yi1 : yi0;
        if (idx < B_*HID_){
          int r = idx & 127, u = idx >> 7;
          int tok = toks[r];
          float4 ev = __ldg((const float4*)&g_E2[((size_t)tok*HID_ + u)*4]);
          float gi = g_base[(size_t)u*B_ + r] + ev.x;
          float gf = g_base[(size_t)(512+u)*B_ + r] + ev.y;
          float gg = g_base[(size_t)(1024+u)*B_ + r] + ev.z;
          float go = g_base[(size_t)(1536+u)*B_ + r] + ev.w;
#pragma unroll
          for (int k = 0; k < 4; ++k){
            const float* pk_ = g_part + (size_t)k*ROWS_*B_;
            gi += __ldcg(pk_ + (size_t)u*B_ + r);
            gf += __ldcg(pk_ + (size_t)(512+u)*B_ + r);
            gg += __ldcg(pk_ + (size_t)(1024+u)*B_ + r);
            go += __ldcg(pk_ + (size_t)(1536+u)*B_ + r);
          }
          gi = 1.f/(1.f + expf(-gi));
          gf = 1.f/(1.f + expf(-gf));
          gg = tanhf(gg);
          go = 1.f/(1.f + expf(-go));
          float cold = q ? cr1 : cr0;
          float cn = fmaf(gf, cold, gi*gg);
          if (q) cr1 = cn; else cr0 = cn;
          float hn = go * tanhf(cn);
          float hi = tf32_rd(hn);
          g_hhi[(size_t)r*HID_ + u] = hi;
          g_hlo[(size_t)r*HID_ + u] = tf32_rd(hn - hi);
          if (m == T_-1){
            out[OUT_H + (size_t)r*HID_ + u] = hn;
            out[OUT_C + (size_t)r*HID_ + u] = cn;
          }
        }
      }
      if (yi0 < B_) g_pack[(m+1) & 1][yi0] = 0ull;
    }
    bt += GRID_; gbar(bt);
  }
}

// ---------------- launch ----------------
extern "C" void kernel_launch(void* const* d_in, const int* in_sizes, int n_in,
                              void* d_out, int out_size){
  const float* ctx  = (const float*)d_in[0];
  const float* emb  = (const float*)d_in[1];
  const float* Wih  = (const float*)d_in[2];
  const float* bih  = (const float*)d_in[3];
  const float* Whh  = (const float*)d_in[4];
  const float* bhh  = (const float*)d_in[5];
  const float* Wout = (const float*)d_in[6];
  const float* bout = (const float*)d_in[7];
  const int*   sid  = (const int*)d_in[8];
  float* out = (float*)d_out;

  cudaFuncSetAttribute(k_persist, cudaFuncAttributeMaxDynamicSharedMemorySize,
                       SMW_ * 4);

  dim3 gE(32, 16);
  k_E<<<gE, 256>>>(emb, Wih);
  k_base<<<128, 256>>>(Wih, bih, bhh, ctx);
  k_init<<<256, 256>>>(ctx, sid);
  k_persist<<<GRID_, NTHR, SMW_ * 4>>>(Whh, Wout, bout, out);
}